// round 17
// baseline (speedup 1.0000x reference)
#include <cuda_runtime.h>
#include <cuda_fp16.h>
#include <math.h>
#include <cstdint>
#include <stdint.h>

#define NN 65535          // number of tree nodes (2^16 - 1)
#define MRPOOL (NN * 8)   // pool GEMM rows
#define BIGF 1e30f

// Packed tile: 128 rows x 64 fp16 K-values (128B/row), SW128-swizzled
// (byte o -> o ^ ((o>>3)&0x70)); 16KB per tile, bulk-copyable verbatim.
__device__ __forceinline__ int swz(int o) { return o ^ ((o >> 3) & 0x70); }

// ---------------- scratch (static device globals; no cudaMalloc) -------------
__device__ __align__(1024) unsigned char g_xpk[(size_t)512 * 5 * 16384]; // packed features (fp16)
__device__ __half g_xg[(size_t)NN * 1024];         // gates pre-activation (fp16)
__device__ __half g_H[(size_t)NN * 256];           // LSTM hidden (fp16)
__device__ __half g_C[(size_t)NN * 256];           // LSTM cell (fp16)
__device__ int   g_mask_is_byte;
__device__ int   g_bar_cnt;                        // fused small-level barrier
__device__ int   g_bar_gen;

// packed weights (fp16)
__device__ __align__(1024) unsigned char g_Wihpk[40 * 16384];  // 8 colblk x 5 chunks (K=320 pad)
__device__ __align__(1024) unsigned char g_Whhpk[32 * 16384];  // 8 jblk x 4 chunks (K=256)
__device__ __align__(1024) unsigned char g_Wbmpk[16 * 16384];  // 16 chunks (K=1024 pad)
__device__ __align__(1024) unsigned char g_Wppk[8192];         // 64 rows x K=64

__device__ __forceinline__ float sigf(float x) { return 1.0f / (1.0f + expf(-x)); }

__device__ __forceinline__ int read_bool(const void* p, int idx) {
    return g_mask_is_byte ? (int)(((const unsigned char*)p)[idx])
                          : (((const int*)p)[idx] != 0);
}

__device__ __forceinline__ unsigned smem_u32(const void* p) {
    return (unsigned)__cvta_generic_to_shared(p);
}

// ---------------- mbarrier + bulk copy ---------------------------------------
#define MBAR_INIT(a) \
    asm volatile("mbarrier.init.shared.b64 [%0], 1;" :: "r"(a) : "memory")
#define MBAR_EXPECT(a, tx) \
    asm volatile("mbarrier.arrive.expect_tx.shared.b64 _, [%0], %1;" \
                 :: "r"(a), "r"(tx) : "memory")

__device__ __forceinline__ void mbar_wait(uint32_t mbar, uint32_t parity) {
    asm volatile(
        "{\n\t.reg .pred P;\n\t"
        "WL%=:\n\t"
        "mbarrier.try_wait.parity.shared.b64 P, [%0], %1;\n\t"
        "@!P bra WL%=;\n\t}"
        :: "r"(mbar), "r"(parity) : "memory");
}

__device__ __forceinline__ void bulk_g2s(uint32_t dst, const void* src,
                                         uint32_t bytes, uint32_t mbar) {
    asm volatile(
        "cp.async.bulk.shared::cluster.global.mbarrier::complete_tx::bytes "
        "[%0], [%1], %2, [%3];"
        :: "r"(dst), "l"(src), "r"(bytes), "r"(mbar) : "memory");
}

// ---------------- fp16 helpers ------------------------------------------------
__device__ __forceinline__ uint32_t packh2(float x, float y) {
    __half2 h = __floats2half2_rn(x, y);
    return *(uint32_t*)&h;
}
__device__ __forceinline__ __half2 u2h(uint32_t u) { return *(__half2*)&u; }
__device__ __forceinline__ uint32_t h2u(__half2 h) { return *(uint32_t*)&h; }

// ---------------- mma.sync m16n8k16 fp16 + ldmatrix --------------------------
__device__ __forceinline__ void mma_f16(float d[4], const uint32_t a[4], const uint32_t b[2]) {
    asm volatile(
        "mma.sync.aligned.m16n8k16.row.col.f32.f16.f16.f32 "
        "{%0,%1,%2,%3}, {%4,%5,%6,%7}, {%8,%9}, {%0,%1,%2,%3};\n"
        : "+f"(d[0]), "+f"(d[1]), "+f"(d[2]), "+f"(d[3])
        : "r"(a[0]), "r"(a[1]), "r"(a[2]), "r"(a[3]), "r"(b[0]), "r"(b[1]));
}

__device__ __forceinline__ void ldsm4(uint32_t r[4], const void* p) {
    uint32_t addr = smem_u32(p);
    asm volatile("ldmatrix.sync.aligned.m8n8.x4.shared.b16 {%0,%1,%2,%3}, [%4];"
                 : "=r"(r[0]), "=r"(r[1]), "=r"(r[2]), "=r"(r[3]) : "r"(addr));
}

// K=64 tile, 32x64 warp tile; NKS k-steps of 16 (4 = full, 2 = half tail)
template <int NKS>
__device__ __forceinline__ void mma_t64(const char* As, const char* Bs,
                                        int wm, int wn, int lane, float acc[2][8][4]) {
    int lrow = lane & 15, l16 = (lane >> 4) * 16;
#pragma unroll
    for (int ks = 0; ks < NKS; ks++) {
        int kb = ks * 32 + l16;
        uint32_t a[2][4];
#pragma unroll
        for (int mt = 0; mt < 2; mt++)
            ldsm4(a[mt], As + swz((wm * 32 + mt * 16 + lrow) * 128 + kb));
#pragma unroll
        for (int g = 0; g < 4; g++) {
            uint32_t b[4];
            ldsm4(b, Bs + swz((wn * 64 + g * 16 + lrow) * 128 + kb));
            uint32_t b0[2] = { b[0], b[2] }, b1[2] = { b[1], b[3] };
#pragma unroll
            for (int mt = 0; mt < 2; mt++) {
                mma_f16(acc[mt][g * 2],     a[mt], b0);
                mma_f16(acc[mt][g * 2 + 1], a[mt], b1);
            }
        }
    }
}

// 1-pass K=64 tile, 32x32 warp tile (pool)
__device__ __forceinline__ void mma_t64_32(const char* As, const char* Bs,
                                           int wm, int wn, int lane, float acc[2][4][4]) {
    int lrow = lane & 15, l16 = (lane >> 4) * 16;
#pragma unroll
    for (int ks = 0; ks < 4; ks++) {
        int kb = ks * 32 + l16;
        uint32_t a[2][4];
#pragma unroll
        for (int mt = 0; mt < 2; mt++)
            ldsm4(a[mt], As + swz((wm * 32 + mt * 16 + lrow) * 128 + kb));
#pragma unroll
        for (int g = 0; g < 2; g++) {
            uint32_t b[4];
            ldsm4(b, Bs + swz((wn * 32 + g * 16 + lrow) * 128 + kb));
            uint32_t b0[2] = { b[0], b[2] }, b1[2] = { b[1], b[3] };
#pragma unroll
            for (int mt = 0; mt < 2; mt++) {
                mma_f16(acc[mt][g * 2],     a[mt], b0);
                mma_f16(acc[mt][g * 2 + 1], a[mt], b1);
            }
        }
    }
}

// ---------------- A-side loaders ----------------------------------------------
__device__ __forceinline__ void ldg_f32u(const float* __restrict__ src, int ld, int rowBase,
                                         int maxRow, int k0, int Ktot, int tid, float4 (*v)[2]) {
#pragma unroll
    for (int s = 0; s < 4; s++) {
        int idx = tid + 256 * s;
        int r = idx >> 3, u = idx & 7;
        int row = rowBase + r, k = k0 + u * 8;
        float4 a = make_float4(0.f, 0.f, 0.f, 0.f), b = a;
        if (row < maxRow && k + 8 <= Ktot) {
            const float* p = src + (size_t)row * ld + k;
            a = *(const float4*)p;
            b = *(const float4*)(p + 4);
        }
        v[s][0] = a; v[s][1] = b;
    }
}

__device__ __forceinline__ void sts_h64(char* As, int tid, float4 (*v)[2]) {
#pragma unroll
    for (int s = 0; s < 4; s++) {
        int idx = tid + 256 * s;
        int r = idx >> 3, u = idx & 7;
        uint4 h;
        h.x = packh2(v[s][0].x, v[s][0].y);
        h.y = packh2(v[s][0].z, v[s][0].w);
        h.z = packh2(v[s][1].x, v[s][1].y);
        h.w = packh2(v[s][1].z, v[s][1].w);
        *(uint4*)(As + swz(r * 128 + u * 16)) = h;
    }
}

// level A: K=64 chunk of averaged child H (fp16 in, fp16 out); 4 slots/thread
__device__ __forceinline__ void ldg_avgH16(int start, int nd, int rowBase, int k0, int tid,
                                           uint4* v) {
    __half2 half2c = __float2half2_rn(0.5f);
#pragma unroll
    for (int s = 0; s < 4; s++) {
        int idx = tid + 256 * s;
        int r = idx >> 3, u = idx & 7;
        int rr = rowBase + r;
        uint4 out = make_uint4(0, 0, 0, 0);
        if (rr < nd) {
            int node = start + rr;
            int ci = 2 * node - NN;
            uint4 A = *(const uint4*)(g_H + (size_t)ci * 256 + k0 + u * 8);
            uint4 B = *(const uint4*)(g_H + (size_t)(ci - 1) * 256 + k0 + u * 8);
            out.x = h2u(__hmul2(__hadd2(u2h(A.x), u2h(B.x)), half2c));
            out.y = h2u(__hmul2(__hadd2(u2h(A.y), u2h(B.y)), half2c));
            out.z = h2u(__hmul2(__hadd2(u2h(A.z), u2h(B.z)), half2c));
            out.w = h2u(__hmul2(__hadd2(u2h(A.w), u2h(B.w)), half2c));
        }
        v[s] = out;
    }
}

__device__ __forceinline__ void sts_u4(char* As, int tid, const uint4* v) {
#pragma unroll
    for (int s = 0; s < 4; s++) {
        int idx = tid + 256 * s;
        int r = idx >> 3, u = idx & 7;
        *(uint4*)(As + swz(r * 128 + u * 16)) = v[s];
    }
}

// ---------------- small kernels ----------------------------------------------
__global__ void k_detect(const unsigned int* __restrict__ m) {
    __shared__ int found;
    if (threadIdx.x == 0) found = 0;
    __syncthreads();
    unsigned int v = m[threadIdx.x];
    if (v > 1u) found = 1;
    __syncthreads();
    if (threadIdx.x == 0) g_mask_is_byte = found;
}

__device__ __forceinline__ void pack8h(const float* s, unsigned char* dst,
                                       int r, int u, bool zero) {
    uint4 h;
    h.x = packh2(zero ? 0.f : s[0], zero ? 0.f : s[1]);
    h.y = packh2(zero ? 0.f : s[2], zero ? 0.f : s[3]);
    h.z = packh2(zero ? 0.f : s[4], zero ? 0.f : s[5]);
    h.w = packh2(zero ? 0.f : s[6], zero ? 0.f : s[7]);
    *(uint4*)(dst + swz(r * 128 + u * 16)) = h;
}

// fork-critical weights: Wbm + Wp
__global__ void k_wpack_fork(const float* __restrict__ Wbm, const float* __restrict__ Wp) {
    int i = blockIdx.x * 256 + threadIdx.x;
    const int N3 = 16 * 1024, N4 = 512;
    if (i < N3) {
        int t = i >> 10, rem = i & 1023, r = rem >> 3, u = rem & 7;
        int k = t * 64 + u * 8;
        bool zero = (k + 8 > 1000);
        pack8h(Wbm + (size_t)r * 1000 + (zero ? 0 : k),
               g_Wbmpk + (size_t)t * 16384, r, u, zero);
    } else if (i < N3 + N4) {
        int j = i - N3;
        int r = j >> 3, u = j & 7;
        pack8h(Wp + (size_t)r * 64 + u * 8, g_Wppk, r, u, false);
    }
}

// later weights: Wih + Whh (needed only by xg / levels)
__global__ void k_wpack_rest(const float* __restrict__ Wih, const float* __restrict__ Whh) {
    int i = blockIdx.x * 256 + threadIdx.x;
    const int N1 = 40 * 1024, N2 = 32 * 1024;
    if (i < N1) {
        int t = i >> 10, rem = i & 1023, r = rem >> 3, u = rem & 7;
        int cb = t / 5, ch = t % 5;
        int k = ch * 64 + u * 8;
        bool zero = (k >= 288);
        pack8h(Wih + (size_t)(cb * 128 + r) * 288 + (zero ? 0 : k),
               g_Wihpk + (size_t)t * 16384, r, u, zero);
    } else if (i < N1 + N2) {
        int j = i - N1;
        int t = j >> 10, rem = j & 1023, r = rem >> 3, u = rem & 7;
        int jb = t / 4, ch = t % 4;
        int wrow = (r >> 5) * 256 + jb * 32 + (r & 31);
        pack8h(Whh + (size_t)wrow * 256 + ch * 64 + u * 8,
               g_Whhpk + (size_t)t * 16384, r, u, false);
    }
}

__global__ void k_op(const float* __restrict__ op_vec,
                     const float* __restrict__ W_op,
                     const float* __restrict__ b_op) {
    __shared__ float Ws[32][33];
    __shared__ float bs[32];
    int tid = threadIdx.x;
    if (tid < 32) bs[tid] = b_op[tid];
    for (int i = tid; i < 1024; i += 256) Ws[i >> 5][i & 31] = W_op[i];
    __syncthreads();
    int node = blockIdx.x * 8 + (tid >> 5);
    int o = tid & 31;
    if (node >= NN) return;
    float vl = op_vec[node * 32 + o];
    float acc = bs[o];
#pragma unroll
    for (int p = 0; p < 32; p++)
        acc += Ws[o][p] * __shfl_sync(0xffffffffu, vl, p);
    int blk = node >> 7, r = node & 127;
    unsigned char* tb = g_xpk + (size_t)blk * 5 * 16384;   // chunk 0
    *(__half*)(tb + swz(r * 128 + o * 2)) = __float2half_rn(acc);
}

// ============ GEMM 1: pool (128Mx64N, single K=64 tile, 1-pass) ==============
__global__ __launch_bounds__(256, 4)
void k_pool_mma(const float* __restrict__ preds1, const void* mask1, const void* and1,
                const float* __restrict__ preds2, const void* mask2, const void* and2,
                const float* __restrict__ b_pred) {
    extern __shared__ char sm[];
    char* Abuf = sm;                 // 16KB
    char* Bbuf = sm + 16384;         // 8KB
    uint32_t mb = smem_u32(sm + 34816);
    float* stage = (float*)sm;       // [128][68] after GEMM (34816B)

    int tid = threadIdx.x, lane = tid & 31, warp = tid >> 5;
    int wm = warp >> 1, wn = warp & 1;
    int cond = blockIdx.y;
    const float* preds = cond ? preds2 : preds1;
    const void*  maskp = cond ? mask2 : mask1;
    const void*  andp  = cond ? and2  : and1;
    int rowBase = blockIdx.x * 128;

    if (tid == 0) MBAR_INIT(mb);
    __syncthreads();
    if (tid == 0) {
        MBAR_EXPECT(mb, 8192u);
        bulk_g2s(smem_u32(Bbuf), g_Wppk, 8192u, mb);
    }

    float acc[2][4][4];
#pragma unroll
    for (int a = 0; a < 2; a++)
#pragma unroll
        for (int b = 0; b < 4; b++)
#pragma unroll
            for (int c = 0; c < 4; c++) acc[a][b][c] = 0.f;

    float4 va[4][2];
    ldg_f32u(preds, 64, rowBase, MRPOOL, 0, 64, tid, va);
    sts_h64(Abuf, tid, va);
    mbar_wait(mb, 0);
    __syncthreads();

    mma_t64_32(Abuf, Bbuf, wm, wn, lane, acc);
    __syncthreads();

#pragma unroll
    for (int mt = 0; mt < 2; mt++) {
#pragma unroll
        for (int nt = 0; nt < 4; nt++) {
            int r = wm * 32 + mt * 16 + (lane >> 2);
            int c = wn * 32 + nt * 8 + (lane & 3) * 2;
            stage[r * 68 + c] = acc[mt][nt][0];
            stage[r * 68 + c + 1] = acc[mt][nt][1];
            stage[(r + 8) * 68 + c] = acc[mt][nt][2];
            stage[(r + 8) * 68 + c + 1] = acc[mt][nt][3];
        }
    }
    __syncthreads();

    int node = blockIdx.x * 16 + (tid >> 4);
    int cg = (tid & 15) * 4;
    if (node < NN) {
        float bb[4];
        *(float4*)bb = *(const float4*)(b_pred + cg);
        int mk[8], anyb = 0;
#pragma unroll
        for (int i = 0; i < 8; i++) { mk[i] = read_bool(maskp, node * 8 + i); anyb |= mk[i]; }
        int ia = read_bool(andp, node);
        int rb = (tid >> 4) * 8;
        float out[4];
#pragma unroll
        for (int j = 0; j < 4; j++) {
            float mn = BIGF, mx = -BIGF;
#pragma unroll
            for (int i = 0; i < 8; i++) {
                float v = stage[(rb + i) * 68 + cg + j] + bb[j];
                if (mk[i]) { mn = fminf(mn, v); mx = fmaxf(mx, v); }
            }
            out[j] = anyb ? (ia ? mn : mx) : 0.0f;
        }
        int col0 = 32 + cond * 64 + cg;
        int ch = col0 >> 6, co = col0 & 63;
        int r = node & 127;
        unsigned char* tb = g_xpk + ((size_t)(node >> 7) * 5 + ch) * 16384;
        *(uint2*)(tb + swz(r * 128 + co * 2)) =
            make_uint2(packh2(out[0], out[1]), packh2(out[2], out[3]));
    }
}

// ============ GEMM 2: bm (128Mx128N, 16 K=64 chunks, 1-pass) =================
__global__ __launch_bounds__(256, 2)
void k_bm_mma(const float* __restrict__ bitmap, const float* __restrict__ b_bm) {
    extern __shared__ char sm[];
    char* Abuf[2] = { sm, sm + 16384 };
    char* Bbuf[2] = { sm + 32768, sm + 49152 };
    uint32_t mb = smem_u32(sm + 65536);
    int tid = threadIdx.x, lane = tid & 31, warp = tid >> 5;
    int wm = warp >> 1, wn = warp & 1;
    int rowBase = blockIdx.x * 128;

    if (tid == 0) { MBAR_INIT(mb); MBAR_INIT(mb + 8); }
    __syncthreads();
    if (tid == 0) {
        MBAR_EXPECT(mb, 16384u);
        bulk_g2s(smem_u32(Bbuf[0]), g_Wbmpk, 16384u, mb);
        MBAR_EXPECT(mb + 8, 16384u);
        bulk_g2s(smem_u32(Bbuf[1]), g_Wbmpk + 16384, 16384u, mb + 8);
    }

    float acc[2][8][4];
#pragma unroll
    for (int a = 0; a < 2; a++)
#pragma unroll
        for (int b = 0; b < 8; b++)
#pragma unroll
            for (int c = 0; c < 4; c++) acc[a][b][c] = 0.f;

    float4 va[4][2];
    ldg_f32u(bitmap, 1000, rowBase, NN, 0, 1000, tid, va);
    sts_h64(Abuf[0], tid, va);
    __syncthreads();

    const int NC = 16;
    for (int t = 0; t < NC; t++) {
        bool more = (t + 1 < NC);
        if (more) ldg_f32u(bitmap, 1000, rowBase, NN, (t + 1) * 64, 1000, tid, va);
        mbar_wait(mb + 8 * (t & 1), (t >> 1) & 1);
        mma_t64<4>(Abuf[t & 1], Bbuf[t & 1], wm, wn, lane, acc);
        if (more) sts_h64(Abuf[(t + 1) & 1], tid, va);
        __syncthreads();
        if (tid == 0 && t + 2 < NC) {
            int s = t + 2, b = s & 1;
            MBAR_EXPECT(mb + 8 * b, 16384u);
            bulk_g2s(smem_u32(Bbuf[b]), g_Wbmpk + (size_t)s * 16384, 16384u, mb + 8 * b);
        }
    }

#pragma unroll
    for (int nt = 0; nt < 8; nt++) {
        int c = wn * 64 + nt * 8 + (lane & 3) * 2;
        float bx = b_bm[c], by = b_bm[c + 1];
        int ch = (160 + c) >> 6, co = (160 + c) & 63;
#pragma unroll
        for (int mt = 0; mt < 2; mt++) {
            int r0 = rowBase + wm * 32 + mt * 16 + (lane >> 2);
#pragma unroll
            for (int hh = 0; hh < 2; hh++) {
                int row = r0 + hh * 8;
                if (row < NN) {
                    int r = row & 127;
                    unsigned char* tb = g_xpk + ((size_t)(row >> 7) * 5 + ch) * 16384;
                    *(uint32_t*)(tb + swz(r * 128 + co * 2)) =
                        packh2(acc[mt][nt][hh * 2] + bx, acc[mt][nt][hh * 2 + 1] + by);
                }
            }
        }
    }
}

// ============ GEMM 3: xg (128Mx128N, 4.5 K=64 chunks, all-bulk) ==============
__global__ __launch_bounds__(256, 2)
void k_xg_mma(const float* __restrict__ b_ih, const float* __restrict__ b_hh) {
    int colBase = blockIdx.x * 128;
    int rowBase = blockIdx.y * 128;
    // f-gate columns [256,512) are never read for leaf nodes (< 32768)
    if ((colBase == 256 || colBase == 384) && rowBase + 128 <= 32768) return;

    extern __shared__ char sm[];
    uint32_t mb = smem_u32(sm + 98304);
    int tid = threadIdx.x, lane = tid & 31, warp = tid >> 5;
    int wm = warp >> 1, wn = warp & 1;
    int cb = colBase >> 7;
    int rb5 = (rowBase >> 7) * 5;

    if (tid == 0) { MBAR_INIT(mb); MBAR_INIT(mb + 8); MBAR_INIT(mb + 16); }
    __syncthreads();
    const int NC = 5;
    if (tid == 0) {
#pragma unroll
        for (int s = 0; s < 3; s++) {
            char* base = sm + s * 32768;
            MBAR_EXPECT(mb + 8 * s, 32768u);
            bulk_g2s(smem_u32(base), g_xpk + ((size_t)rb5 + s) * 16384, 16384u, mb + 8 * s);
            bulk_g2s(smem_u32(base + 16384), g_Wihpk + ((size_t)cb * 5 + s) * 16384,
                     16384u, mb + 8 * s);
        }
    }

    float acc[2][8][4];
#pragma unroll
    for (int a = 0; a < 2; a++)
#pragma unroll
        for (int b = 0; b < 8; b++)
#pragma unroll
            for (int c = 0; c < 4; c++) acc[a][b][c] = 0.f;

    for (int t = 0; t < NC; t++) {
        int b = t % 3;
        mbar_wait(mb + 8 * b, (uint32_t)((t / 3) & 1));
        if (t < 4)
            mma_t64<4>(sm + b * 32768, sm + b * 32768 + 16384, wm, wn, lane, acc);
        else
            mma_t64<2>(sm + b * 32768, sm + b * 32768 + 16384, wm, wn, lane, acc);
        __syncthreads();
        if (tid == 0 && t + 3 < NC) {
            int s = t + 3;
            char* base = sm + b * 32768;
            MBAR_EXPECT(mb + 8 * b, 32768u);
            bulk_g2s(smem_u32(base), g_xpk + ((size_t)rb5 + s) * 16384, 16384u, mb + 8 * b);
            bulk_g2s(smem_u32(base + 16384), g_Wihpk + ((size_t)cb * 5 + s) * 16384,
                     16384u, mb + 8 * b);
        }
    }

#pragma unroll
    for (int nt = 0; nt < 8; nt++) {
        int c = colBase + wn * 64 + nt * 8 + (lane & 3) * 2;
        float bx = b_ih[c] + b_hh[c], by = b_ih[c + 1] + b_hh[c + 1];
#pragma unroll
        for (int mt = 0; mt < 2; mt++) {
            int r0 = rowBase + wm * 32 + mt * 16 + (lane >> 2);
            if (r0 < NN)
                *(uint32_t*)(g_xg + (size_t)r0 * 1024 + c) =
                    packh2(acc[mt][nt][0] + bx, acc[mt][nt][1] + by);
            if (r0 + 8 < NN)
                *(uint32_t*)(g_xg + (size_t)(r0 + 8) * 1024 + c) =
                    packh2(acc[mt][nt][2] + bx, acc[mt][nt][3] + by);
        }
    }
}

// ============ level kernel (nd >= 128): 1-pass fp16 + LSTM pointwise =========
__global__ __launch_bounds__(256, 2)
void k_level_mma(int start, int nd) {
    extern __shared__ char sm[];
    char* Abuf[2] = { sm, sm + 16384 };
    char* Bbuf[2] = { sm + 32768, sm + 49152 };
    uint32_t mb = smem_u32(sm + 67584);
    float* stage = (float*)sm;   // [128][132] after GEMM (67584B)

    int tid = threadIdx.x, lane = tid & 31, warp = tid >> 5;
    int wm = warp >> 1, wn = warp & 1;
    int rowBase = blockIdx.x * 128;
    int jb = blockIdx.y;          // j block (32 wide)

    if (tid == 0) { MBAR_INIT(mb); MBAR_INIT(mb + 8); }
    __syncthreads();
    if (tid == 0) {
        MBAR_EXPECT(mb, 16384u);
        bulk_g2s(smem_u32(Bbuf[0]), g_Whhpk + (size_t)(jb * 4) * 16384, 16384u, mb);
        MBAR_EXPECT(mb + 8, 16384u);
        bulk_g2s(smem_u32(Bbuf[1]), g_Whhpk + (size_t)(jb * 4 + 1) * 16384, 16384u, mb + 8);
    }

    float acc[2][8][4];
#pragma unroll
    for (int a = 0; a < 2; a++)
#pragma unroll
        for (int b = 0; b < 8; b++)
#pragma unroll
            for (int c = 0; c < 4; c++) acc[a][b][c] = 0.f;

    uint4 va[4];
    ldg_avgH16(start, nd, rowBase, 0, tid, va);
    sts_u4(Abuf[0], tid, va);
    __syncthreads();

    const int NC = 4;   // K=64 chunks
    for (int t = 0; t < NC; t++) {
        bool more = (t + 1 < NC);
        if (more) ldg_avgH16(start, nd, rowBase, (t + 1) * 64, tid, va);
        mbar_wait(mb + 8 * (t & 1), (t >> 1) & 1);
        mma_t64<4>(Abuf[t & 1], Bbuf[t & 1], wm, wn, lane, acc);
        if (more) sts_u4(Abuf[(t + 1) & 1], tid, va);
        __syncthreads();
        if (tid == 0 && t + 2 < NC) {
            int s = t + 2, b = s & 1;
            MBAR_EXPECT(mb + 8 * b, 16384u);
            bulk_g2s(smem_u32(Bbuf[b]), g_Whhpk + (size_t)(jb * 4 + s) * 16384,
                     16384u, mb + 8 * b);
        }
    }

#pragma unroll
    for (int mt = 0; mt < 2; mt++) {
#pragma unroll
        for (int nt = 0; nt < 8; nt++) {
            int r = wm * 32 + mt * 16 + (lane >> 2);
            int c = wn * 64 + nt * 8 + (lane & 3) * 2;
            stage[r * 132 + c] = acc[mt][nt][0];
            stage[r * 132 + c + 1] = acc[mt][nt][1];
            stage[(r + 8) * 132 + c] = acc[mt][nt][2];
            stage[(r + 8) * 132 + c + 1] = acc[mt][nt][3];
        }
    }
    __syncthreads();

#pragma unroll
    for (int i = 0; i < 16; i++) {
        int idx = tid + 256 * i;
        int r = idx >> 5, jj = idx & 31;
        int rr = rowBase + r;
        if (rr < nd) {
            int node = start + rr;
            int j = jb * 32 + jj;
            const __half* xr = g_xg + (size_t)node * 1024;
            float gi = stage[r * 132 + jj]       + __half2float(xr[j]);
            float gf = stage[r * 132 + 32 + jj]  + __half2float(xr[256 + j]);
            float gg = stage[r * 132 + 64 + jj]  + __half2float(xr[512 + j]);
            float go = stage[r * 132 + 96 + jj]  + __half2float(xr[768 + j]);
            int ci = 2 * node - NN;
            float c0 = 0.5f * (__half2float(g_C[(size_t)ci * 256 + j]) +
                               __half2float(g_C[(size_t)(ci - 1) * 256 + j]));
            float cn = sigf(gf) * c0 + sigf(gi) * tanhf(gg);
            float hn = sigf(go) * tanhf(cn);
            g_H[(size_t)node * 256 + j] = __float2half_rn(hn);
            g_C[(size_t)node * 256 + j] = __float2half_rn(cn);
        }
    }
}

// ---------------- leaves (d = D): c0 = 0 -------------------------------------
__global__ void k_leaf() {
    int n = blockIdx.x;
    int j = threadIdx.x;
    const __half* xr = g_xg + (size_t)n * 1024;
    float gi = __half2float(xr[j]);
    float gg = __half2float(xr[512 + j]);
    float go = __half2float(xr[768 + j]);
    float c = sigf(gi) * tanhf(gg);
    float h = sigf(go) * tanhf(c);
    g_H[(size_t)n * 256 + j] = __float2half_rn(h);
    g_C[(size_t)n * 256 + j] = __float2half_rn(c);
}

// ---------------- fused small-level kernel (d = 6..0), 8 blocks --------------
__device__ __forceinline__ void level_body(
    float (*h0s)[36], float (*Ws)[36],
    int start, int nd, int rowBase, int jbase,
    const float* __restrict__ W_hh)
{
    int tid = threadIdx.x;
    int jx = tid & 63, ry = tid >> 6;

    float acc[8][4];
#pragma unroll
    for (int i = 0; i < 8; i++)
#pragma unroll
        for (int g = 0; g < 4; g++) acc[i][g] = 0.0f;

    for (int k0 = 0; k0 < 256; k0 += 32) {
        {
            int r = tid >> 3, c4 = tid & 7;
            float4 v = make_float4(0.f, 0.f, 0.f, 0.f);
            int rr = rowBase + r;
            if (rr < nd) {
                int node = start + rr;
                int ci = 2 * node - NN;
                const __half2* a2 = (const __half2*)&g_H[(size_t)ci * 256 + k0 + c4 * 4];
                const __half2* b2 = (const __half2*)&g_H[(size_t)(ci - 1) * 256 + k0 + c4 * 4];
                float2 a0 = __half22float2(a2[0]), a1 = __half22float2(a2[1]);
                float2 b0 = __half22float2(b2[0]), b1 = __half22float2(b2[1]);
                v = make_float4(0.5f * (a0.x + b0.x), 0.5f * (a0.y + b0.y),
                                0.5f * (a1.x + b1.x), 0.5f * (a1.y + b1.y));
            }
            *(float4*)&h0s[r][c4 * 4] = v;
        }
        {
            int wrow = ry * 256 + jbase + jx;
            const float* src = &W_hh[(size_t)wrow * 256 + k0];
#pragma unroll
            for (int c = 0; c < 8; c++)
                *(float4*)&Ws[tid][c * 4] = *(const float4*)&src[c * 4];
        }
        __syncthreads();
#pragma unroll
        for (int kk4 = 0; kk4 < 8; kk4++) {
            float4 w4[4];
#pragma unroll
            for (int g = 0; g < 4; g++)
                w4[g] = *(const float4*)&Ws[g * 64 + jx][kk4 * 4];
#pragma unroll
            for (int i = 0; i < 8; i++) {
                float4 a4 = *(const float4*)&h0s[ry * 8 + i][kk4 * 4];
#pragma unroll
                for (int g = 0; g < 4; g++)
                    acc[i][g] += a4.x * w4[g].x + a4.y * w4[g].y +
                                 a4.z * w4[g].z + a4.w * w4[g].w;
            }
        }
        __syncthreads();
    }

    int j = jbase + jx;
#pragma unroll
    for (int i = 0; i < 8; i++) {
        int rr = rowBase + ry * 8 + i;
        if (rr < nd) {
            int node = start + rr;
            const __half* xr = g_xg + (size_t)node * 1024;
            float gi = acc[i][0] + __half2float(xr[j]);
            float gf = acc[i][1] + __half2float(xr[256 + j]);
            float gg = acc[i][2] + __half2float(xr[512 + j]);
            float go = acc[i][3] + __half2float(xr[768 + j]);
            int ci = 2 * node - NN;
            float c0 = 0.5f * (__half2float(g_C[(size_t)ci * 256 + j]) +
                               __half2float(g_C[(size_t)(ci - 1) * 256 + j]));
            float cn = sigf(gf) * c0 + sigf(gi) * tanhf(gg);
            float hn = sigf(go) * tanhf(cn);
            g_H[(size_t)node * 256 + j] = __float2half_rn(hn);
            g_C[(size_t)node * 256 + j] = __float2half_rn(cn);
        }
    }
}

__global__ __launch_bounds__(256)
void k_levels_small(const float* __restrict__ W_hh) {
    __shared__ float h0s[32][36];
    __shared__ float Ws[256][36];
    int b = blockIdx.x;           // 0..7
    int rb = b & 1, jbx = b >> 1; // 2 row-blocks x 4 col-blocks

    for (int d = 6; d >= 0; d--) {
        int nd = 1 << d;
        int start = NN - (1 << (d + 1)) + 1;
        if (rb * 32 < nd)
            level_body(h0s, Ws, start, nd, rb * 32, jbx * 64, W_hh);
        // inter-block barrier (all 8 blocks resident; generation counting)
        __syncthreads();
        __threadfence();
        if (threadIdx.x == 0) {
            int g = atomicAdd(&g_bar_gen, 0);
            int c = atomicAdd(&g_bar_cnt, 1);
            if (c == 7) {
                g_bar_cnt = 0;
                __threadfence();
                atomicAdd(&g_bar_gen, 1);
            } else {
                while (atomicAdd(&g_bar_gen, 0) == g) { }
            }
        }
        __syncthreads();
        __threadfence();
    }
}

// ---------------- output heads ----------------------------------------------
__global__ void k_heads(const float* __restrict__ W2a, const float* __restrict__ b2a,
                        const float* __restrict__ W3a, const float* __restrict__ b3a,
                        const float* __restrict__ Woa, const float* __restrict__ boa,
                        const float* __restrict__ W2b, const float* __restrict__ b2b,
                        const float* __restrict__ W3b, const float* __restrict__ b3b,
                        const float* __restrict__ Wob, const float* __restrict__ bob,
                        float* __restrict__ out) {
    __shared__ float hv[256];
    __shared__ float t1[2][128];
    __shared__ float t2[2][128];
    __shared__ float red[256];
    int tid = threadIdx.x;
    hv[tid] = __half2float(g_H[(size_t)(NN - 1) * 256 + tid]);
    __syncthreads();
    int head = tid >> 7, j = tid & 127;
    const float* W2 = head ? W2b : W2a; const float* b2 = head ? b2b : b2a;
    const float* W3 = head ? W3b : W3a; const float* b3 = head ? b3b : b3a;
    const float* Wo = head ? Wob : Woa; const float* bo = head ? bob : boa;

    float t = b2[j];
    for (int k = 0; k < 256; k++) t += W2[j * 256 + k] * hv[k];
    t1[head][j] = fmaxf(t, 0.0f);
    __syncthreads();
    t = b3[j];
    for (int k = 0; k < 128; k++) t += W3[j * 128 + k] * t1[head][k];
    t2[head][j] = fmaxf(t, 0.0f);
    __syncthreads();
    red[tid] = Wo[j] * t2[head][j];
    __syncthreads();
    for (int s = 64; s > 0; s >>= 1) {
        if (j < s) red[tid] += red[tid + s];
        __syncthreads();
    }
    if (j == 0) out[head] = 1.0f / (1.0f + expf(-(red[tid] + bo[0])));
}

// ---------------- launch ------------------------------------------------------
extern "C" void kernel_launch(void* const* d_in, const int* in_sizes, int n_in,
                              void* d_out, int out_size) {
    const float* op_vec   = (const float*)d_in[0];
    const float* c1_preds = (const float*)d_in[1];
    const void*  c1_mask  = d_in[2];
    const void*  c1_and   = d_in[3];
    const float* c2_preds = (const float*)d_in[4];
    const void*  c2_mask  = d_in[5];
    const void*  c2_and   = d_in[6];
    const float* bitmap   = (const float*)d_in[7];
    const float* W_op     = (const float*)d_in[8];
    const float* b_op     = (const float*)d_in[9];
    const float* W_pred   = (const float*)d_in[10];
    const float* b_pred   = (const float*)d_in[11];
    const float* W_bm     = (const float*)d_in[12];
    const float* b_bm     = (const float*)d_in[13];
    const float* W_ih     = (const float*)d_in[14];
    const float* b_ih     = (const float*)d_in[15];
    const float* W_hh     = (const float*)d_in[16];
    const float* b_hh     = (const float*)d_in[17];
    const float* W_h2t1   = (const float*)d_in[18];
    const float* b_h2t1   = (const float*)d_in[19];
    const float* W_h3t1   = (const float*)d_in[20];
    const float* b_h3t1   = (const float*)d_in[21];
    const float* W_o1     = (const float*)d_in[22];
    const float* b_o1     = (const float*)d_in[23];
    const float* W_h2t2   = (const float*)d_in[24];
    const float* b_h2t2   = (const float*)d_in[25];
    const float* W_h3t2   = (const float*)d_in[26];
    const float* b_h3t2   = (const float*)d_in[27];
    const float* W_o2     = (const float*)d_in[28];
    const float* b_o2     = (const float*)d_in[29];
    float* out = (float*)d_out;

    const int SM_PL = 34816 + 64;
    const int SM_BM = 65536 + 64;
    const int SM_XG = 98304 + 64;
    const int SM_LV = 67584 + 64;
    static int configured = 0;
    static cudaStream_t s1, s2;
    static cudaEvent_t evRoot, evFork, ev1, ev2;
    if (!configured) {
        cudaFuncSetAttribute(k_pool_mma, cudaFuncAttributeMaxDynamicSharedMemorySize, SM_PL);
        cudaFuncSetAttribute(k_bm_mma,   cudaFuncAttributeMaxDynamicSharedMemorySize, SM_BM);
        cudaFuncSetAttribute(k_xg_mma,   cudaFuncAttributeMaxDynamicSharedMemorySize, SM_XG);
        cudaFuncSetAttribute(k_level_mma,cudaFuncAttributeMaxDynamicSharedMemorySize, SM_LV);
        cudaStreamCreateWithFlags(&s1, cudaStreamNonBlocking);
        cudaStreamCreateWithFlags(&s2, cudaStreamNonBlocking);
        cudaEventCreateWithFlags(&evRoot, cudaEventDisableTiming);
        cudaEventCreateWithFlags(&evFork, cudaEventDisableTiming);
        cudaEventCreateWithFlags(&ev1, cudaEventDisableTiming);
        cudaEventCreateWithFlags(&ev2, cudaEventDisableTiming);
        configured = 1;
    }

    // ---- fork s2 from the capture origin FIRST (graph-capture topology rule),
    //      then run its independent chain: op -> Wih/Whh packing ----
    cudaEventRecord(evRoot, 0);
    cudaStreamWaitEvent(s2, evRoot, 0);
    k_op<<<(NN + 7) / 8, 256, 0, s2>>>(op_vec, W_op, b_op);
    k_wpack_rest<<<(40 * 1024 + 32 * 1024 + 255) / 256, 256, 0, s2>>>(W_ih, W_hh);

    // ---- s0 prologue: only the weights the fork branches consume ----
    k_detect<<<1, 256>>>((const unsigned int*)c1_mask);
    k_wpack_fork<<<(16 * 1024 + 512 + 255) / 256, 256>>>(W_bm, W_pred);

    cudaEventRecord(evFork, 0);
    cudaStreamWaitEvent(s1, evFork, 0);

    // branch 0 (default stream): pool (DRAM-stream bound)
    {
        dim3 grid((MRPOOL + 127) / 128, 2);
        k_pool_mma<<<grid, 256, SM_PL>>>(c1_preds, c1_mask, c1_and,
                                         c2_preds, c2_mask, c2_and, b_pred);
    }

    // branch 1 (s1): bm (tensor bound)
    k_bm_mma<<<(NN + 127) / 128, 256, SM_BM, s1>>>(bitmap, b_bm);

    // ---- join ----
    cudaEventRecord(ev1, s1);
    cudaEventRecord(ev2, s2);
    cudaStreamWaitEvent(0, ev1, 0);
    cudaStreamWaitEvent(0, ev2, 0);

    {
        dim3 grid(8, (NN + 127) / 128);
        k_xg_mma<<<grid, 256, SM_XG>>>(b_ih, b_hh);
    }

    k_leaf<<<32768, 256>>>();

    for (int d = 14; d >= 7; d--) {
        int nd = 1 << d;
        int start = NN - (1 << (d + 1)) + 1;
        dim3 grid((nd + 127) / 128, 8);
        k_level_mma<<<grid, 256, SM_LV>>>(start, nd);
    }

    k_levels_small<<<8, 256>>>(W_hh);

    k_heads<<<1, 256>>>(W_h2t1, b_h2t1, W_h3t1, b_h3t1, W_o1, b_o1,
                        W_h2t2, b_h2t2, W_h3t2, b_h3t2, W_o2, b_o2,
                        out);
}